// round 12
// baseline (speedup 1.0000x reference)
#include <cuda_runtime.h>

// GaussianEdgeGuide — prep kernel + smem-free, halo-free full-width stencil.
//
// Algebra: softmax over the 9 neighborhood positions of
//   -theta*(edge_center + edge_neighbor - max_edge)
// has edge_center and max_edge constant along the softmax axis, so
//   weight_k(q) = E(q+d_k) / S(q),   E(x) = exp(-theta*edge(x)) (E=1 outside),
//   S(q) = sum_k E(q+d_k).
// One iteration: mask'(q) = box3(mask*E)(q) / S(q)   (mask zero-padded).
// iter1 = box3(mask*E) * IE  (IE = W*E),  out = box3(iter1) * W.
//
// Stencil: each warp spans the full 256-px row: lane l owns 4-px groups at
// x=4l (g0) and x=128+4l (g1) -> contiguous LDG.128s; the only horizontal
// boundary is the true image border (zero shuffle-in) plus the 127<->128
// seam (two warp broadcasts). No halo loads/state/predicates.
//
// R11 post-mortem: halo-free warp is ~1.7x more efficient per warp, but
// 80 regs x 64-thr CTAs packed to only 26% occ (1.37 ragged waves). This
// round: __launch_bounds__(64,16) -> 64-reg cap -> 16 CTAs/SM = 50% occ,
// 1.02 waves. Minor spills land in an L1 at 28%.

#define NB   8
#define NC   19
#define HW   256
#define NPIX (HW * HW)

__device__ __align__(16) float g_E [NB * NPIX];   // exp(-40*edge)
__device__ __align__(16) float g_W [NB * NPIX];   // 1 / box3(E)
__device__ __align__(16) float g_IE[NB * NPIX];   // W * E

// ---------------------------------------------------------------------------
// Kernel 1: per-pixel E, W, IE (32x32 tiles; unchanged).
// ---------------------------------------------------------------------------
__global__ __launch_bounds__(256, 4)
void geg_prep(const float* __restrict__ edge)
{
    __shared__ float sE[34 * 35];   // 34x34 E with halo 1, E=1 outside image

    const int tid = threadIdx.x;
    const int h0 = blockIdx.y * 32, w0 = blockIdx.x * 32;
    const int n  = blockIdx.z;
    const float* eimg = edge + (n << 16);

    for (int idx = tid; idx < 34 * 34; idx += 256) {
        int i = idx / 34, j = idx - i * 34;
        int gy = h0 - 1 + i, gx = w0 - 1 + j;
        float e = 1.0f;  // exp(-40 * 0) at zero-padded border
        if ((unsigned)gy < 256u && (unsigned)gx < 256u)
            e = __expf(-40.0f * eimg[(gy << 8) + gx]);
        sE[i * 35 + j] = e;
    }
    __syncthreads();

    const int tj = tid & 31, tb = tid >> 5;
    #pragma unroll
    for (int k = 0; k < 4; ++k) {
        int ti = tb + 8 * k;
        const float* p = &sE[ti * 35 + tj];
        float s = p[0]  + p[1]  + p[2]
                + p[35] + p[36] + p[37]
                + p[70] + p[71] + p[72];
        float w  = __fdividef(1.0f, s);
        float ec = p[36];
        int g = (n << 16) + ((h0 + ti) << 8) + (w0 + tj);
        g_E [g] = ec;
        g_W [g] = w;
        g_IE[g] = w * ec;
    }
}

// ---------------------------------------------------------------------------
// Kernel 2: halo-free stencil. Grid (16, NB*NC), block 64 (2 warps).
// Warp owns 8 output rows of the full 256-px width.
// ---------------------------------------------------------------------------
__global__ __launch_bounds__(64, 16)
void geg_stencil(const float* __restrict__ mask,
                 float* __restrict__ out)
{
    const unsigned FULL = 0xffffffffu;
    const int lane = threadIdx.x & 31;
    const int warp = threadIdx.x >> 5;     // 0..1
    const int z    = blockIdx.y;           // n * NC + c
    const int n    = z / NC;

    const float4* mch = (const float4*)(mask + ((size_t)z << 16));
    float4*       och = (float4*)(out  + ((size_t)z << 16));
    const float4* Eb  = (const float4*)(g_E  + (n << 16));
    const float4* IEb = (const float4*)(g_IE + (n << 16));
    const float4* Wb  = (const float4*)(g_W  + (n << 16));

    const int qa = lane;        // f4 col of g0 (px 4*lane)        + row*64
    const int qb = 32 + lane;   // f4 col of g1 (px 128 + 4*lane)  + row*64

    const int R0 = (blockIdx.x << 4) + (warp << 3);  // first output row

    // --- rolling state: P rows (mask*E) and iter1 rows, 2 groups each ---
    float4 a0, a1, a2;   // g0 P rows
    float4 b0, b1, b2;   // g1 P rows
    float4 m0, m1, m2;   // g0 iter1 rows
    float4 u0, u1, u2;   // g1 iter1 rows

    // prologue: P rows R0-2, R0-1 (zero when above the image)
    {
        int gy = R0 - 2;
        if ((unsigned)gy < 256u) {
            float4 m = mch[(gy << 6) + qa], e = Eb[(gy << 6) + qa];
            a0 = make_float4(m.x*e.x, m.y*e.y, m.z*e.z, m.w*e.w);
            m = mch[(gy << 6) + qb]; e = Eb[(gy << 6) + qb];
            b0 = make_float4(m.x*e.x, m.y*e.y, m.z*e.z, m.w*e.w);
        } else {
            a0 = make_float4(0.f, 0.f, 0.f, 0.f);
            b0 = make_float4(0.f, 0.f, 0.f, 0.f);
        }
        gy = R0 - 1;
        if ((unsigned)gy < 256u) {
            float4 m = mch[(gy << 6) + qa], e = Eb[(gy << 6) + qa];
            a1 = make_float4(m.x*e.x, m.y*e.y, m.z*e.z, m.w*e.w);
            m = mch[(gy << 6) + qb]; e = Eb[(gy << 6) + qb];
            b1 = make_float4(m.x*e.x, m.y*e.y, m.z*e.z, m.w*e.w);
        } else {
            a1 = make_float4(0.f, 0.f, 0.f, 0.f);
            b1 = make_float4(0.f, 0.f, 0.f, 0.f);
        }
    }
    // never read before written (first output at a=R0+1 reads m0 from a=R0-1)
    m1 = m2 = u1 = u2 = make_float4(0.f, 0.f, 0.f, 0.f);

    #pragma unroll
    for (int a = R0 - 1; a <= R0 + 8; ++a) {   // iter1 row a
        // load P row a+1
        int gy = a + 1;
        if ((unsigned)gy < 256u) {
            float4 m = mch[(gy << 6) + qa], e = Eb[(gy << 6) + qa];
            a2 = make_float4(m.x*e.x, m.y*e.y, m.z*e.z, m.w*e.w);
            m = mch[(gy << 6) + qb]; e = Eb[(gy << 6) + qb];
            b2 = make_float4(m.x*e.x, m.y*e.y, m.z*e.z, m.w*e.w);
        } else {
            a2 = make_float4(0.f, 0.f, 0.f, 0.f);
            b2 = make_float4(0.f, 0.f, 0.f, 0.f);
        }

        // vertical 3-sums at row a, both groups (independent chains)
        float c1 = a0.x + a1.x + a2.x;
        float c2 = a0.y + a1.y + a2.y;
        float c3 = a0.z + a1.z + a2.z;
        float c4 = a0.w + a1.w + a2.w;
        float d1 = b0.x + b1.x + b2.x;
        float d2 = b0.y + b1.y + b2.y;
        float d3 = b0.z + b1.z + b2.z;
        float d4 = b0.w + b1.w + b2.w;

        // horizontal exchange: neighbors + the 127<->128 seam broadcasts
        float l0 = __shfl_up_sync  (FULL, c4, 1);
        float r0 = __shfl_down_sync(FULL, c1, 1);
        float l1 = __shfl_up_sync  (FULL, d4, 1);
        float r1 = __shfl_down_sync(FULL, d1, 1);
        float s0 = __shfl_sync(FULL, c4, 31);  // px 127 sum
        float s1 = __shfl_sync(FULL, d1, 0);   // px 128 sum
        if (lane == 0)  { l0 = 0.f; l1 = s0; } // px -1 -> zero-pad
        if (lane == 31) { r0 = s1; r1 = 0.f; } // px 256 -> zero-pad

        // iter1 row a (zero outside image)
        float4 mrow, urow;
        if ((unsigned)a < 256u) {
            float4 ie = IEb[(a << 6) + qa];
            mrow.x = (l0 + c1 + c2) * ie.x;
            mrow.y = (c1 + c2 + c3) * ie.y;
            mrow.z = (c2 + c3 + c4) * ie.z;
            mrow.w = (c3 + c4 + r0) * ie.w;
            ie = IEb[(a << 6) + qb];
            urow.x = (l1 + d1 + d2) * ie.x;
            urow.y = (d1 + d2 + d3) * ie.y;
            urow.z = (d2 + d3 + d4) * ie.z;
            urow.w = (d3 + d4 + r1) * ie.w;
        } else {
            mrow = make_float4(0.f, 0.f, 0.f, 0.f);
            urow = make_float4(0.f, 0.f, 0.f, 0.f);
        }

        // roll
        a0 = a1; a1 = a2;
        b0 = b1; b1 = b2;
        m0 = m1; m1 = m2; m2 = mrow;
        u0 = u1; u1 = u2; u2 = urow;

        if (a >= R0 + 1) {
            int r = a - 1;                    // output row, in [0,255]
            float v1 = m0.x + m1.x + m2.x;
            float v2 = m0.y + m1.y + m2.y;
            float v3 = m0.z + m1.z + m2.z;
            float v4 = m0.w + m1.w + m2.w;
            float w1 = u0.x + u1.x + u2.x;
            float w2 = u0.y + u1.y + u2.y;
            float w3 = u0.z + u1.z + u2.z;
            float w4 = u0.w + u1.w + u2.w;

            float L0 = __shfl_up_sync  (FULL, v4, 1);
            float Rr0 = __shfl_down_sync(FULL, v1, 1);
            float L1 = __shfl_up_sync  (FULL, w4, 1);
            float Rr1 = __shfl_down_sync(FULL, w1, 1);
            float S0 = __shfl_sync(FULL, v4, 31);
            float S1 = __shfl_sync(FULL, w1, 0);
            if (lane == 0)  { L0 = 0.f; L1 = S0; }
            if (lane == 31) { Rr0 = S1; Rr1 = 0.f; }

            float4 wgt = Wb[(r << 6) + qa];
            float4 o;
            o.x = (L0 + v1 + v2) * wgt.x;
            o.y = (v1 + v2 + v3) * wgt.y;
            o.z = (v2 + v3 + v4) * wgt.z;
            o.w = (v3 + v4 + Rr0) * wgt.w;
            och[(r << 6) + qa] = o;

            wgt = Wb[(r << 6) + qb];
            o.x = (L1 + w1 + w2) * wgt.x;
            o.y = (w1 + w2 + w3) * wgt.y;
            o.z = (w2 + w3 + w4) * wgt.z;
            o.w = (w3 + w4 + Rr1) * wgt.w;
            och[(r << 6) + qb] = o;
        }
    }
}

extern "C" void kernel_launch(void* const* d_in, const int* in_sizes, int n_in,
                              void* d_out, int out_size)
{
    const float* mask = (const float*)d_in[0];
    const float* edge = (const float*)d_in[1];
    // d_in[2] = iter_n is fixed at 2 by the problem setup; 2 iterations fused.
    (void)in_sizes; (void)n_in; (void)out_size;

    dim3 gp(HW / 32, HW / 32, NB);            // 8 x 8 x 8
    geg_prep<<<gp, 256>>>(edge);

    dim3 gs(HW / 16, NB * NC);                // 16 x 152 = 2432 CTAs
    geg_stencil<<<gs, 64>>>(mask, (float*)d_out);
}